// round 15
// baseline (speedup 1.0000x reference)
#include <cuda_runtime.h>
#include <cstdint>

#define N_NODES 50000
#define N_EDGES 800000
#define NTILE 782          // 64-node GEMM tiles

typedef unsigned long long ull;

// ---------------- device globals (no allocation allowed) --------------------
__device__ int   g_deg[N_NODES];
__device__ int   g_off[N_NODES + 1];
__device__ int   g_cur[N_NODES];
__device__ int   g_bsum[64];
__device__ int   g_esrc[N_EDGES];
__device__ float g_mean[(size_t)N_NODES * 96];
__device__ float g_h1[(size_t)N_NODES * 96];
__device__ float g_y[(size_t)N_NODES * 96];     // layer2 projection [yl48|yr48]

__device__ __forceinline__ int clampN(int v) {
    return v < 0 ? 0 : (v >= N_NODES ? N_NODES - 1 : v);
}

// ---- packed f32x2 (FFMA2 via PTX) -------------------------------------------
__device__ __forceinline__ ull pack2(float x, float y) {
    ull r; asm("mov.b64 %0, {%1, %2};" : "=l"(r) : "f"(x), "f"(y)); return r;
}
__device__ __forceinline__ ull fma2(ull a, ull b, ull c) {
    ull d; asm("fma.rn.f32x2 %0, %1, %2, %3;" : "=l"(d) : "l"(a), "l"(b), "l"(c)); return d;
}
__device__ __forceinline__ float2 unpack2(ull v) {
    float2 f; asm("mov.b64 {%0, %1}, %2;" : "=f"(f.x), "=f"(f.y) : "l"(v)); return f;
}

// ---------------- CSR build ----------------------------------------------------
__global__ void k_zero() {
    int i = blockIdx.x * blockDim.x + threadIdx.x;
    if (i < N_NODES) g_deg[i] = 0;
}
__global__ void k_count(const int* __restrict__ ei) {
    int e = blockIdx.x * blockDim.x + threadIdx.x;
    if (e < N_EDGES) atomicAdd(&g_deg[clampN(ei[N_EDGES + e])], 1);
}
__global__ void k_scan1() {
    __shared__ int s[1024];
    int i = blockIdx.x * 1024 + threadIdx.x;
    int v = (i < N_NODES) ? g_deg[i] : 0;
    s[threadIdx.x] = v;
    __syncthreads();
    for (int d = 1; d < 1024; d <<= 1) {
        int t = (threadIdx.x >= d) ? s[threadIdx.x - d] : 0;
        __syncthreads();
        s[threadIdx.x] += t;
        __syncthreads();
    }
    if (i < N_NODES) g_off[i] = s[threadIdx.x] - v;
    if (threadIdx.x == 1023) g_bsum[blockIdx.x] = s[1023];
}
__global__ void k_scan3() {
    __shared__ int sb[64];
    __shared__ int base;
    int t = threadIdx.x;
    if (t < 64) sb[t] = (t < blockIdx.x) ? g_bsum[t] : 0;
    __syncthreads();
    if (t == 0) {
        int a = 0;
        #pragma unroll
        for (int b = 0; b < 64; b++) a += sb[b];
        base = a;
    }
    __syncthreads();
    int i = blockIdx.x * 1024 + t;
    if (i < N_NODES) { int o = g_off[i] + base; g_off[i] = o; g_cur[i] = o; }
    if (i == 0) g_off[N_NODES] = N_EDGES;
}
__global__ void k_fill(const int* __restrict__ ei) {
    int e = blockIdx.x * blockDim.x + threadIdx.x;
    if (e < N_EDGES) {
        int s = clampN(ei[e]);
        int d = clampN(ei[N_EDGES + e]);
        int p = atomicAdd(&g_cur[d], 1);
        if (p >= 0 && p < N_EDGES) g_esrc[p] = s;
    }
}

// ---------------- mean aggregation (96-wide), warp per node -------------------
template <int SRC>  // 0 = ext(x), 1 = g_h1
__global__ void k_agg(const float* __restrict__ ext) {
    const float* hin = SRC == 1 ? g_h1 : ext;
    int w    = (blockIdx.x * blockDim.x + threadIdx.x) >> 5;
    int lane = threadIdx.x & 31;
    if (w >= N_NODES) return;
    int beg = g_off[w], end = g_off[w + 1];
    float a0 = 0.f, a1 = 0.f, a2 = 0.f;
    int e = beg;
    for (; e + 3 < end; e += 4) {
        const float* r0 = hin + (size_t)g_esrc[e]     * 96;
        const float* r1 = hin + (size_t)g_esrc[e + 1] * 96;
        const float* r2 = hin + (size_t)g_esrc[e + 2] * 96;
        const float* r3 = hin + (size_t)g_esrc[e + 3] * 96;
        a0 += (r0[lane]      + r1[lane])      + (r2[lane]      + r3[lane]);
        a1 += (r0[lane + 32] + r1[lane + 32]) + (r2[lane + 32] + r3[lane + 32]);
        a2 += (r0[lane + 64] + r1[lane + 64]) + (r2[lane + 64] + r3[lane + 64]);
    }
    for (; e < end; e++) {
        const float* r0 = hin + (size_t)g_esrc[e] * 96;
        a0 += r0[lane]; a1 += r0[lane + 32]; a2 += r0[lane + 64];
    }
    int deg = end - beg;
    float inv = 1.0f / (float)(deg > 0 ? deg : 1);
    float* o = g_mean + (size_t)w * 96;
    o[lane] = a0 * inv; o[lane + 32] = a1 * inv; o[lane + 64] = a2 * inv;
}

// ---- GEMM building blocks -----------------------------------------------------
// sW*: float[32][96]; sM/sH: ull[64][33] activations pre-duplicated (m,m).
// Thread tile 4 rows x 12 cols; 128 threads; TN=64 nodes/block.
#define GEMM_LOADW(dst, Wp, kc) \
    for (int idx = tid; idx < 32 * 24; idx += 128) { \
        int kk = idx / 24, j4 = idx % 24; \
        *(float4*)&dst[kk][j4 * 4] = *(const float4*)&Wp[((kc) + kk) * 96 + j4 * 4]; \
    }
#define GEMM_LOADA_DUP(dst, inp, kc) \
    for (int idx = tid; idx < 64 * 8; idx += 128) { \
        int ii = idx >> 3, q = idx & 7; \
        int row = clampN(node0 + ii); \
        float4 v = *(const float4*)&inp[(size_t)row * 96 + (kc) + q * 4]; \
        dst[ii][q*4+0] = pack2(v.x, v.x); dst[ii][q*4+1] = pack2(v.y, v.y); \
        dst[ii][q*4+2] = pack2(v.z, v.z); dst[ii][q*4+3] = pack2(v.w, v.w); \
    }
// weights via LDS.128 (ulonglong2): 3 loads per matrix per k, no MOVs
#define LOADW6(w, sWx, k) { \
    ulonglong2 u0 = *(const ulonglong2*)&sWx[k][j0]; \
    ulonglong2 u1 = *(const ulonglong2*)&sWx[k][j0 + 4]; \
    ulonglong2 u2 = *(const ulonglong2*)&sWx[k][j0 + 8]; \
    w[0] = u0.x; w[1] = u0.y; w[2] = u1.x; w[3] = u1.y; w[4] = u2.x; w[5] = u2.y; }

#define DUAL_INNER() \
    _Pragma("unroll 2") \
    for (int k = 0; k < 32; k++) { \
        ull wl[6], wr[6]; \
        LOADW6(wl, sWl, k) \
        LOADW6(wr, sWr, k) \
        _Pragma("unroll") \
        for (int r = 0; r < 4; r++) { \
            ull m2 = sM[ig * 4 + r][k]; \
            ull h2 = sH[ig * 4 + r][k]; \
            _Pragma("unroll") \
            for (int p = 0; p < 6; p++) \
                acc[r][p] = fma2(m2, wl[p], fma2(h2, wr[p], acc[r][p])); \
        } \
    }

// ---- gemm0: g_h1 = relu(g_mean@Wl0 + x@Wr0 + b0) ------------------------------
__global__ void __launch_bounds__(128, 3) k_gemm0(
    const float* __restrict__ x,
    const float* __restrict__ Wl, const float* __restrict__ Wr,
    const float* __restrict__ bias)
{
    __shared__ float sWl[32][96];
    __shared__ float sWr[32][96];
    __shared__ ull   sM[64][33];
    __shared__ ull   sH[64][33];

    int tid = threadIdx.x;
    int jg = tid % 8, ig = tid / 8;
    int j0 = jg * 12;
    int node0 = blockIdx.x * 64;

    ull acc[4][6];
    #pragma unroll
    for (int r = 0; r < 4; r++)
        #pragma unroll
        for (int p = 0; p < 6; p++) acc[r][p] = 0ull;

    for (int kc = 0; kc < 96; kc += 32) {
        __syncthreads();
        GEMM_LOADW(sWl, Wl, kc)
        GEMM_LOADW(sWr, Wr, kc)
        GEMM_LOADA_DUP(sM, g_mean, kc)
        GEMM_LOADA_DUP(sH, x, kc)
        __syncthreads();
        DUAL_INNER()
    }

    #pragma unroll
    for (int r = 0; r < 4; r++) {
        int node = node0 + ig * 4 + r;
        if (node < N_NODES) {
            float* o = g_h1 + (size_t)node * 96 + j0;
            #pragma unroll
            for (int p = 0; p < 6; p++) {
                float2 v = unpack2(acc[r][p]);
                float2 b = *(const float2*)&bias[j0 + 2 * p];
                float2 s;
                s.x = fmaxf(v.x + b.x, 0.f);
                s.y = fmaxf(v.y + b.y, 0.f);
                *(float2*)&o[2 * p] = s;
            }
        }
    }
}

// ---- gemm1+proj: h2 = relu(mean@Wl1 + h1@Wr1 + b1) in smem,
//      then g_y = [h2@Wl2 | h2@Wr2 + b2] ---------------------------------------
__global__ void __launch_bounds__(128, 2) k_gemm1_proj(
    const float* __restrict__ Wl1, const float* __restrict__ Wr1,
    const float* __restrict__ b1,
    const float* __restrict__ Wl2, const float* __restrict__ Wr2,
    const float* __restrict__ b2)
{
    __shared__ float sWl[32][96];
    __shared__ float sWr[32][96];
    __shared__ ull   sM[64][33];
    __shared__ ull   sH[64][33];
    __shared__ ull   h2b[64][49];    // h2 as float2-packed pairs (48 per row + pad)

    int tid = threadIdx.x;
    int jg = tid % 8, ig = tid / 8;
    int j0 = jg * 12;
    int node0 = blockIdx.x * 64;

    ull acc[4][6];
    #pragma unroll
    for (int r = 0; r < 4; r++)
        #pragma unroll
        for (int p = 0; p < 6; p++) acc[r][p] = 0ull;

    // phase A: dual GEMM for h2
    for (int kc = 0; kc < 96; kc += 32) {
        __syncthreads();
        GEMM_LOADW(sWl, Wl1, kc)
        GEMM_LOADW(sWr, Wr1, kc)
        GEMM_LOADA_DUP(sM, g_mean, kc)
        GEMM_LOADA_DUP(sH, g_h1, kc)
        __syncthreads();
        DUAL_INNER()
    }

    // h2 = relu(acc + b1) -> smem (float2-packed, k-pairs)
    __syncthreads();
    #pragma unroll
    for (int r = 0; r < 4; r++) {
        int row = ig * 4 + r;
        #pragma unroll
        for (int p = 0; p < 6; p++) {
            float2 v = unpack2(acc[r][p]);
            float2 b = *(const float2*)&b1[j0 + 2 * p];
            float sx = fmaxf(v.x + b.x, 0.f);
            float sy = fmaxf(v.y + b.y, 0.f);
            h2b[row][(j0 + 2 * p) >> 1] = pack2(sx, sy);
        }
        #pragma unroll
        for (int p = 0; p < 6; p++) acc[r][p] = 0ull;
    }

    // phase B: g_y = [h2@Wl2 | h2@Wr2 + b2]   (weights concat into sWl)
    for (int kc = 0; kc < 96; kc += 32) {
        __syncthreads();
        for (int idx = tid; idx < 32 * 24; idx += 128) {
            int kk = idx / 24, j4 = idx % 24;
            int j = j4 * 4;
            float4 v = (j < 48) ? *(const float4*)&Wl2[(kc + kk) * 48 + j]
                                : *(const float4*)&Wr2[(kc + kk) * 48 + (j - 48)];
            *(float4*)&sWl[kk][j] = v;
        }
        __syncthreads();

        #pragma unroll 2
        for (int k = 0; k < 32; k++) {
            ull w[6];
            LOADW6(w, sWl, k)
            #pragma unroll
            for (int r = 0; r < 4; r++) {
                ull pair = h2b[ig * 4 + r][(kc + k) >> 1];
                float2 hp = unpack2(pair);
                float hv = ((kc + k) & 1) ? hp.y : hp.x;
                ull a2 = pack2(hv, hv);
                #pragma unroll
                for (int p = 0; p < 6; p++)
                    acc[r][p] = fma2(a2, w[p], acc[r][p]);
            }
        }
    }

    #pragma unroll
    for (int r = 0; r < 4; r++) {
        int node = node0 + ig * 4 + r;
        if (node < N_NODES) {
            float* o = g_y + (size_t)node * 96 + j0;
            #pragma unroll
            for (int p = 0; p < 6; p++) {
                float2 v = unpack2(acc[r][p]);
                int c = j0 + 2 * p;
                if (c >= 48) { v.x += b2[c - 48]; v.y += b2[c - 47]; }
                *(float2*)&o[2 * p] = v;
            }
        }
    }
}

// ---- final 48-wide aggregation + relu ------------------------------------------
__global__ void k_agg48(float* __restrict__ out) {
    int w    = (blockIdx.x * blockDim.x + threadIdx.x) >> 5;
    int lane = threadIdx.x & 31;
    if (w >= N_NODES) return;
    int beg = g_off[w], end = g_off[w + 1];
    float a0 = 0.f, a1 = 0.f, b0 = 0.f, b1 = 0.f;
    int e = beg;
    for (; e + 7 < end; e += 8) {
        const float* r0 = g_y + (size_t)g_esrc[e]     * 96;
        const float* r1 = g_y + (size_t)g_esrc[e + 1] * 96;
        const float* r2 = g_y + (size_t)g_esrc[e + 2] * 96;
        const float* r3 = g_y + (size_t)g_esrc[e + 3] * 96;
        const float* r4 = g_y + (size_t)g_esrc[e + 4] * 96;
        const float* r5 = g_y + (size_t)g_esrc[e + 5] * 96;
        const float* r6 = g_y + (size_t)g_esrc[e + 6] * 96;
        const float* r7 = g_y + (size_t)g_esrc[e + 7] * 96;
        a0 += (r0[lane] + r1[lane]) + (r2[lane] + r3[lane]);
        b0 += (r4[lane] + r5[lane]) + (r6[lane] + r7[lane]);
        if (lane < 16) {
            a1 += (r0[32+lane] + r1[32+lane]) + (r2[32+lane] + r3[32+lane]);
            b1 += (r4[32+lane] + r5[32+lane]) + (r6[32+lane] + r7[32+lane]);
        }
    }
    for (; e < end; e++) {
        const float* r0 = g_y + (size_t)g_esrc[e] * 96;
        a0 += r0[lane];
        if (lane < 16) a1 += r0[32 + lane];
    }
    a0 += b0; a1 += b1;
    int deg = end - beg;
    float inv = 1.0f / (float)(deg > 0 ? deg : 1);
    const float* yr = g_y + (size_t)w * 96 + 48;
    float* o = out + (size_t)w * 48;
    o[lane] = fmaxf(a0 * inv + yr[lane], 0.f);
    if (lane < 16) o[32 + lane] = fmaxf(a1 * inv + yr[32 + lane], 0.f);
}

// ---------------- launch ----------------------------------------------------------
extern "C" void kernel_launch(void* const* d_in, const int* in_sizes, int n_in,
                              void* d_out, int out_size)
{
    const float* x   = (const float*)d_in[0];
    const int*   ei  = (const int*)d_in[1];     // int32 (JAX x64 disabled)
    const float* Wl0 = (const float*)d_in[2];
    const float* Wr0 = (const float*)d_in[3];
    const float* b0  = (const float*)d_in[4];
    const float* Wl1 = (const float*)d_in[5];
    const float* Wr1 = (const float*)d_in[6];
    const float* b1  = (const float*)d_in[7];
    const float* Wl2 = (const float*)d_in[8];
    const float* Wr2 = (const float*)d_in[9];
    const float* b2  = (const float*)d_in[10];
    float*       out = (float*)d_out;

    const int nScanBlk = (N_NODES + 1023) / 1024;   // 49
    const int nEdgeBlk = (N_EDGES + 255) / 256;     // 3125
    const int aggBlk   = (N_NODES + 7) / 8;         // 6250

    // CSR build
    k_zero<<<(N_NODES + 255) / 256, 256>>>();
    k_count<<<nEdgeBlk, 256>>>(ei);
    k_scan1<<<nScanBlk, 1024>>>();
    k_scan3<<<nScanBlk, 1024>>>();
    k_fill<<<nEdgeBlk, 256>>>(ei);

    // layer 0
    k_agg<0><<<aggBlk, 256>>>(x);
    k_gemm0<<<NTILE, 128>>>(x, Wl0, Wr0, b0);
    // layer 1 + layer 2 projection (fused through smem)
    k_agg<1><<<aggBlk, 256>>>(nullptr);
    k_gemm1_proj<<<NTILE, 128>>>(Wl1, Wr1, b1, Wl2, Wr2, b2);
    // final 48-wide aggregation
    k_agg48<<<aggBlk, 256>>>(out);
}

// round 16
// speedup vs baseline: 1.1934x; 1.1934x over previous
#include <cuda_runtime.h>
#include <cuda_bf16.h>
#include <cstdint>

#define N_NODES 50000
#define N_EDGES 800000
#define FIN 96

typedef unsigned long long ull;

// ---------------- scratch (device globals; no allocation allowed) ----------
__device__ int   g_deg[N_NODES];
__device__ int   g_off[N_NODES + 1];
__device__ int   g_cur[N_NODES];
__device__ int   g_bsum[64];
__device__ int   g_esrc[N_EDGES];
__device__ float g_mean[(size_t)N_NODES * FIN];
__device__ float g_h1[(size_t)N_NODES * FIN];
__device__ float g_h2[(size_t)N_NODES * FIN];
__device__ float g_y[(size_t)N_NODES * FIN];   // layer2 projection: [yl(48) | yr(48)]

__device__ __forceinline__ int clampN(int v) {
    return v < 0 ? 0 : (v >= N_NODES ? N_NODES - 1 : v);
}

// ---- packed f32x2 helpers (FFMA2 via PTX) -----------------------------------
__device__ __forceinline__ ull pack2(float x, float y) {
    ull r;
    asm("mov.b64 %0, {%1, %2};" : "=l"(r) : "f"(x), "f"(y));
    return r;
}
__device__ __forceinline__ ull fma2(ull a, ull b, ull c) {
    ull d;
    asm("fma.rn.f32x2 %0, %1, %2, %3;" : "=l"(d) : "l"(a), "l"(b), "l"(c));
    return d;
}
__device__ __forceinline__ float2 unpack2(ull v) {
    float2 f;
    asm("mov.b64 {%0, %1}, %2;" : "=f"(f.x), "=f"(f.y) : "l"(v));
    return f;
}

// ---------------- CSR build ---------------------------------------------------
__global__ void k_zero_deg() {
    int i = blockIdx.x * blockDim.x + threadIdx.x;
    if (i < N_NODES) g_deg[i] = 0;
}
__global__ void k_count(const int* __restrict__ ei) {
    int e = blockIdx.x * blockDim.x + threadIdx.x;
    if (e < N_EDGES) atomicAdd(&g_deg[clampN(ei[N_EDGES + e])], 1);
}
__global__ void k_scan1() {
    __shared__ int s[1024];
    int i = blockIdx.x * 1024 + threadIdx.x;
    int v = (i < N_NODES) ? g_deg[i] : 0;
    s[threadIdx.x] = v;
    __syncthreads();
    for (int d = 1; d < 1024; d <<= 1) {
        int t = (threadIdx.x >= d) ? s[threadIdx.x - d] : 0;
        __syncthreads();
        s[threadIdx.x] += t;
        __syncthreads();
    }
    if (i < N_NODES) g_off[i] = s[threadIdx.x] - v;
    if (threadIdx.x == 1023) g_bsum[blockIdx.x] = s[1023];
}
__global__ void k_scan3() {
    __shared__ int sb[64];
    __shared__ int base;
    int t = threadIdx.x;
    if (t < 64) sb[t] = (t < blockIdx.x) ? g_bsum[t] : 0;
    __syncthreads();
    if (t == 0) {
        int a = 0;
        #pragma unroll
        for (int b = 0; b < 64; b++) a += sb[b];
        base = a;
    }
    __syncthreads();
    int i = blockIdx.x * 1024 + t;
    if (i < N_NODES) { int o = g_off[i] + base; g_off[i] = o; g_cur[i] = o; }
    if (i == 0) g_off[N_NODES] = N_EDGES;
}
__global__ void k_fill(const int* __restrict__ ei) {
    int e = blockIdx.x * blockDim.x + threadIdx.x;
    if (e < N_EDGES) {
        int s = clampN(ei[e]);
        int d = clampN(ei[N_EDGES + e]);
        int p = atomicAdd(&g_cur[d], 1);
        if (p >= 0 && p < N_EDGES) g_esrc[p] = s;
    }
}

// ---------------- mean aggregation (96-wide), warp per node -----------------
template <int SRC>  // 0 = ext(x), 1 = g_h1
__global__ void k_agg(const float* __restrict__ ext) {
    const float* hin = SRC == 1 ? g_h1 : ext;
    int w    = (blockIdx.x * blockDim.x + threadIdx.x) >> 5;
    int lane = threadIdx.x & 31;
    if (w >= N_NODES) return;
    int beg = g_off[w], end = g_off[w + 1];
    float a0 = 0.f, a1 = 0.f, a2 = 0.f;
    int e = beg;
    for (; e + 3 < end; e += 4) {
        const float* r0 = hin + (size_t)g_esrc[e]     * FIN;
        const float* r1 = hin + (size_t)g_esrc[e + 1] * FIN;
        const float* r2 = hin + (size_t)g_esrc[e + 2] * FIN;
        const float* r3 = hin + (size_t)g_esrc[e + 3] * FIN;
        a0 += (r0[lane]      + r1[lane])      + (r2[lane]      + r3[lane]);
        a1 += (r0[lane + 32] + r1[lane + 32]) + (r2[lane + 32] + r3[lane + 32]);
        a2 += (r0[lane + 64] + r1[lane + 64]) + (r2[lane + 64] + r3[lane + 64]);
    }
    for (; e < end; e++) {
        const float* r0 = hin + (size_t)g_esrc[e] * FIN;
        a0 += r0[lane]; a1 += r0[lane + 32]; a2 += r0[lane + 64];
    }
    int deg = end - beg;
    float inv = 1.0f / (float)(deg > 0 ? deg : 1);
    float* o = g_mean + (size_t)w * FIN;
    o[lane] = a0 * inv; o[lane + 32] = a1 * inv; o[lane + 64] = a2 * inv;
}

// ---------------- dual-GEMM + bias + ReLU (layers 0/1), FFMA2 ----------------
// R8 kernel; ONLY change: weights loaded as ull (LDS.64) instead of float2+pack2.
template <int LAYER>  // 0: x -> g_h1, 1: g_h1 -> g_h2
__global__ void __launch_bounds__(128) k_gemm(
    const float* __restrict__ ext_in,
    const float* __restrict__ Wl, const float* __restrict__ Wr,
    const float* __restrict__ bias)
{
    const float* hin  = (LAYER == 0) ? ext_in : g_h1;
    float*       outp = (LAYER == 0) ? g_h1 : g_h2;

    constexpr int TN = 64;
    constexpr int KC = 32;

    __shared__ float sWl[KC][96];
    __shared__ float sWr[KC][96];
    __shared__ float sM[TN][KC + 1];
    __shared__ float sH[TN][KC + 1];

    int tid = threadIdx.x;
    int jg  = tid % 8;          // 8 col groups of 12
    int ig  = tid / 8;          // 16 node groups of 4
    int j0  = jg * 12;
    int node0 = blockIdx.x * TN;

    ull acc[4][6];
    #pragma unroll
    for (int r = 0; r < 4; r++)
        #pragma unroll
        for (int p = 0; p < 6; p++) acc[r][p] = 0ull;

    for (int kc = 0; kc < FIN; kc += KC) {
        __syncthreads();
        #pragma unroll
        for (int idx = tid; idx < KC * 24; idx += 128) {
            int kk = idx / 24, j4 = idx % 24;
            float4 vl = *(const float4*)&Wl[(kc + kk) * 96 + j4 * 4];
            float4 vr = *(const float4*)&Wr[(kc + kk) * 96 + j4 * 4];
            *(float4*)&sWl[kk][j4 * 4] = vl;
            *(float4*)&sWr[kk][j4 * 4] = vr;
        }
        #pragma unroll
        for (int idx = tid; idx < TN * (KC / 4); idx += 128) {
            int ii = idx / (KC / 4), q = idx % (KC / 4);
            int row = clampN(node0 + ii);
            size_t base = (size_t)row * FIN + kc + q * 4;
            float4 m = *(const float4*)&g_mean[base];
            float4 h = *(const float4*)&hin[base];
            sM[ii][q*4+0]=m.x; sM[ii][q*4+1]=m.y; sM[ii][q*4+2]=m.z; sM[ii][q*4+3]=m.w;
            sH[ii][q*4+0]=h.x; sH[ii][q*4+1]=h.y; sH[ii][q*4+2]=h.z; sH[ii][q*4+3]=h.w;
        }
        __syncthreads();

        #pragma unroll 2
        for (int k = 0; k < KC; k++) {
            ull wl[6], wr[6];
            #pragma unroll
            for (int p = 0; p < 6; p++) {
                wl[p] = *(const ull*)&sWl[k][j0 + 2 * p];   // LDS.64, no MOV
                wr[p] = *(const ull*)&sWr[k][j0 + 2 * p];   // LDS.64, no MOV
            }
            #pragma unroll
            for (int r = 0; r < 4; r++) {
                int ii = ig * 4 + r;
                float mv = sM[ii][k];
                float hv = sH[ii][k];
                ull m2 = pack2(mv, mv);
                ull h2 = pack2(hv, hv);
                #pragma unroll
                for (int p = 0; p < 6; p++)
                    acc[r][p] = fma2(m2, wl[p], fma2(h2, wr[p], acc[r][p]));
            }
        }
    }

    float2 bj[6];
    #pragma unroll
    for (int p = 0; p < 6; p++) bj[p] = *(const float2*)&bias[j0 + 2 * p];

    #pragma unroll
    for (int r = 0; r < 4; r++) {
        int node = node0 + ig * 4 + r;
        if (node < N_NODES) {
            float* o = outp + (size_t)node * 96 + j0;
            #pragma unroll
            for (int p = 0; p < 6; p++) {
                float2 v = unpack2(acc[r][p]);
                float2 s;
                s.x = fmaxf(v.x + bj[p].x, 0.f);
                s.y = fmaxf(v.y + bj[p].y, 0.f);
                *(float2*)&o[2 * p] = s;
            }
        }
    }
}

// ---------------- layer 2 projection: g_y = [h2@Wl2 | h2@Wr2 + b2] ----------
__global__ void __launch_bounds__(128) k_gemm2(
    const float* __restrict__ Wl2, const float* __restrict__ Wr2,
    const float* __restrict__ bias)
{
    constexpr int TN = 64;
    constexpr int KC = 32;

    __shared__ float sW[KC][96];
    __shared__ float sH[TN][KC + 1];
    __shared__ float sB[48];

    int tid = threadIdx.x;
    int jg  = tid % 8;
    int ig  = tid / 8;
    int j0  = jg * 12;
    int node0 = blockIdx.x * TN;

    if (tid < 48) sB[tid] = bias[tid];

    ull acc[4][6];
    #pragma unroll
    for (int r = 0; r < 4; r++)
        #pragma unroll
        for (int p = 0; p < 6; p++) acc[r][p] = 0ull;

    for (int kc = 0; kc < FIN; kc += KC) {
        __syncthreads();
        #pragma unroll
        for (int idx = tid; idx < KC * 24; idx += 128) {
            int kk = idx / 24, j4 = idx % 24;
            int j = j4 * 4;
            float4 v = (j < 48) ? *(const float4*)&Wl2[(kc + kk) * 48 + j]
                                : *(const float4*)&Wr2[(kc + kk) * 48 + (j - 48)];
            *(float4*)&sW[kk][j] = v;
        }
        #pragma unroll
        for (int idx = tid; idx < TN * (KC / 4); idx += 128) {
            int ii = idx / (KC / 4), q = idx % (KC / 4);
            int row = clampN(node0 + ii);
            size_t base = (size_t)row * FIN + kc + q * 4;
            float4 h = *(const float4*)&g_h2[base];
            sH[ii][q*4+0]=h.x; sH[ii][q*4+1]=h.y; sH[ii][q*4+2]=h.z; sH[ii][q*4+3]=h.w;
        }
        __syncthreads();

        #pragma unroll 2
        for (int k = 0; k < KC; k++) {
            ull w[6];
            #pragma unroll
            for (int p = 0; p < 6; p++)
                w[p] = *(const ull*)&sW[k][j0 + 2 * p];     // LDS.64, no MOV
            #pragma unroll
            for (int r = 0; r < 4; r++) {
                float hv = sH[ig * 4 + r][k];
                ull h2 = pack2(hv, hv);
                #pragma unroll
                for (int p = 0; p < 6; p++)
                    acc[r][p] = fma2(h2, w[p], acc[r][p]);
            }
        }
    }

    // epilogue: cols < 48 raw (yl), cols >= 48 add bias (yr). No relu here.
    #pragma unroll
    for (int r = 0; r < 4; r++) {
        int node = node0 + ig * 4 + r;
        if (node < N_NODES) {
            float* o = g_y + (size_t)node * 96 + j0;
            #pragma unroll
            for (int p = 0; p < 6; p++) {
                float2 v = unpack2(acc[r][p]);
                int c = j0 + 2 * p;
                if (c >= 48) { v.x += sB[c - 48]; v.y += sB[c - 47]; }
                *(float2*)&o[2 * p] = v;
            }
        }
    }
}

// ---------------- final 48-wide aggregation + relu (8-edge unroll) ----------
__global__ void k_agg48(float* __restrict__ out) {
    int w    = (blockIdx.x * blockDim.x + threadIdx.x) >> 5;
    int lane = threadIdx.x & 31;
    if (w >= N_NODES) return;
    int beg = g_off[w], end = g_off[w + 1];
    float a0 = 0.f, a1 = 0.f;   // cols [0,32), [32,48)
    float b0 = 0.f, b1 = 0.f;   // second accumulation tree
    int e = beg;
    for (; e + 7 < end; e += 8) {
        const float* r0 = g_y + (size_t)g_esrc[e]     * 96;
        const float* r1 = g_y + (size_t)g_esrc[e + 1] * 96;
        const float* r2 = g_y + (size_t)g_esrc[e + 2] * 96;
        const float* r3 = g_y + (size_t)g_esrc[e + 3] * 96;
        const float* r4 = g_y + (size_t)g_esrc[e + 4] * 96;
        const float* r5 = g_y + (size_t)g_esrc[e + 5] * 96;
        const float* r6 = g_y + (size_t)g_esrc[e + 6] * 96;
        const float* r7 = g_y + (size_t)g_esrc[e + 7] * 96;
        a0 += (r0[lane] + r1[lane]) + (r2[lane] + r3[lane]);
        b0 += (r4[lane] + r5[lane]) + (r6[lane] + r7[lane]);
        if (lane < 16) {
            a1 += (r0[32 + lane] + r1[32 + lane]) + (r2[32 + lane] + r3[32 + lane]);
            b1 += (r4[32 + lane] + r5[32 + lane]) + (r6[32 + lane] + r7[32 + lane]);
        }
    }
    for (; e < end; e++) {
        const float* r0 = g_y + (size_t)g_esrc[e] * 96;
        a0 += r0[lane];
        if (lane < 16) a1 += r0[32 + lane];
    }
    a0 += b0; a1 += b1;
    int deg = end - beg;
    float inv = 1.0f / (float)(deg > 0 ? deg : 1);
    const float* yr = g_y + (size_t)w * 96 + 48;
    float* o = out + (size_t)w * 48;
    o[lane] = fmaxf(a0 * inv + yr[lane], 0.f);
    if (lane < 16) o[32 + lane] = fmaxf(a1 * inv + yr[32 + lane], 0.f);
}

// ---------------- launch ------------------------------------------------------
extern "C" void kernel_launch(void* const* d_in, const int* in_sizes, int n_in,
                              void* d_out, int out_size)
{
    const float* x   = (const float*)d_in[0];
    const int*   ei  = (const int*)d_in[1];     // int32 (JAX x64 disabled)
    const float* Wl0 = (const float*)d_in[2];
    const float* Wr0 = (const float*)d_in[3];
    const float* b0  = (const float*)d_in[4];
    const float* Wl1 = (const float*)d_in[5];
    const float* Wr1 = (const float*)d_in[6];
    const float* b1  = (const float*)d_in[7];
    const float* Wl2 = (const float*)d_in[8];
    const float* Wr2 = (const float*)d_in[9];
    const float* b2  = (const float*)d_in[10];
    float*       out = (float*)d_out;

    const int nScanBlk = (N_NODES + 1023) / 1024;   // 49
    const int nEdgeBlk = (N_EDGES + 255) / 256;     // 3125
    const int aggBlk   = (N_NODES + 7) / 8;         // warp per node
    const int gemmBlk  = (N_NODES + 63) / 64;       // 782

    // CSR build
    k_zero_deg<<<(N_NODES + 255) / 256, 256>>>();
    k_count<<<nEdgeBlk, 256>>>(ei);
    k_scan1<<<nScanBlk, 1024>>>();
    k_scan3<<<nScanBlk, 1024>>>();
    k_fill<<<nEdgeBlk, 256>>>(ei);

    // layer 0
    k_agg<0><<<aggBlk, 256>>>(x);
    k_gemm<0><<<gemmBlk, 128>>>(x, Wl0, Wr0, b0);
    // layer 1
    k_agg<1><<<aggBlk, 256>>>(nullptr);
    k_gemm<1><<<gemmBlk, 128>>>(nullptr, Wl1, Wr1, b1);
    // layer 2: project first (linearity of mean), then 48-wide aggregate
    k_gemm2<<<gemmBlk, 128>>>(Wl2, Wr2, b2);
    k_agg48<<<aggBlk, 256>>>(out);
}